// round 15
// baseline (speedup 1.0000x reference)
#include <cuda_runtime.h>
#include <cuda_fp16.h>
#include <cstdint>

#define NN 50000
#define NE 800000
#define NF 512
#define NH 64
#define NCHUNK ((NN + 255) / 256)   // 196 scan chunks

// B chunk fragment-pair layout: 16 blocks (ks,tig) x 136 words (+8 skew)
#define BBLK 136
#define BCH  (16 * BBLK)            // 2176 words per chunk (padded)
#define BGCH 2048                   // words per chunk in global g_bt (unpadded)

// ---------------- scratch (static device globals; no runtime alloc) ---------
__device__ float    g_h  [NN * NH];  // layer-1 linear output (fp32)
__device__ float    g_h2 [NN * NH];  // layer-2 linear output (fp32)
__device__ __half2  g_hh [NN * 32];  // fp16 mirror of g_h  (gather source)
__device__ __half2  g_hh2[NN * 32];  // fp16 mirror of g_h2 (gather source)
__device__ float    g_deg  [NN];
__device__ float    g_dinv [NN];
__device__ float    g_selfc[NN];
__device__ int      g_src [NE];
__device__ int      g_dst [NE];
__device__ int      g_cnt [NN];
__device__ int      g_cur [NN];
__device__ int      g_rowptr[NN + 1];
__device__ int      g_part  [NCHUNK];
__device__ int      g_partpre[NCHUNK];
__device__ int      g_csrc [NE];
__device__ float    g_ccoef[NE];
__device__ int      g_is32;
__device__ unsigned g_bt1[16 * BGCH]; // W1 tf32, fragment-pair chunk layout
__device__ unsigned g_bt2[2  * BGCH]; // W2 tf32, fragment-pair chunk layout

__device__ __forceinline__ unsigned tf32_rna(float f) {
    unsigned r;
    asm("cvt.rna.tf32.f32 %0, %1;" : "=r"(r) : "f"(f));
    return r;
}
__device__ __forceinline__ void cp_async16(uint32_t saddr, const void* gptr) {
    asm volatile("cp.async.cg.shared.global [%0], [%1], 16;"
                 :: "r"(saddr), "l"(gptr) : "memory");
}

// ---------------- prep branch (side stream) -----------------------------------
__global__ void k_prep0() {
    int i = blockIdx.x * blockDim.x + threadIdx.x;
    if (i == 0) g_is32 = 0;
    if (i < NN) { g_deg[i] = 1.0f; g_cnt[i] = 0; g_cur[i] = 0; }
}
__global__ void k_detect(const int* __restrict__ ei32) {
    int i = blockIdx.x * blockDim.x + threadIdx.x;
    if (i < 8192 && (i & 1) == 1 && ei32[i] != 0) atomicOr(&g_is32, 1);
}
__global__ void k_edge_prep(const void* __restrict__ eiv,
                            const float* __restrict__ ew) {
    int e = blockIdx.x * blockDim.x + threadIdx.x;
    if (e >= NE) return;
    int s, d;
    if (g_is32) {
        const int* p = (const int*)eiv;
        s = p[e]; d = p[NE + e];
    } else {
        const long long* p = (const long long*)eiv;
        s = (int)p[e]; d = (int)p[NE + e];
    }
    if ((unsigned)s >= NN) s = 0;
    if ((unsigned)d >= NN) d = 0;
    g_src[e] = s; g_dst[e] = d;
    atomicAdd(&g_deg[d], ew[e]);
    atomicAdd(&g_cnt[d], 1);
}
__global__ void k_dinv() {
    int i = blockIdx.x * blockDim.x + threadIdx.x;
    if (i < NN) {
        float dv = rsqrtf(g_deg[i]);
        g_dinv[i]  = dv;
        g_selfc[i] = dv * dv;
    }
}
__global__ void k_scanA() {
    __shared__ int sh[256];
    int i = blockIdx.x * 256 + threadIdx.x;
    sh[threadIdx.x] = (i < NN) ? g_cnt[i] : 0;
    __syncthreads();
    for (int o = 128; o > 0; o >>= 1) {
        if (threadIdx.x < o) sh[threadIdx.x] += sh[threadIdx.x + o];
        __syncthreads();
    }
    if (threadIdx.x == 0) g_part[blockIdx.x] = sh[0];
}
__global__ void k_scanB() {
    __shared__ int sh[256];
    int t = threadIdx.x;
    int v = (t < NCHUNK) ? g_part[t] : 0;
    sh[t] = v;
    __syncthreads();
#pragma unroll
    for (int o = 1; o < 256; o <<= 1) {
        int u = (t >= o) ? sh[t - o] : 0;
        __syncthreads();
        sh[t] += u;
        __syncthreads();
    }
    if (t < NCHUNK) g_partpre[t] = sh[t] - v;
    if (t == 255) g_rowptr[NN] = NE;
}
__global__ void k_scanC() {
    __shared__ int sh[256];
    int i = blockIdx.x * 256 + threadIdx.x;
    int t = threadIdx.x;
    int v = (i < NN) ? g_cnt[i] : 0;
    sh[t] = v;
    __syncthreads();
#pragma unroll
    for (int o = 1; o < 256; o <<= 1) {
        int u = (t >= o) ? sh[t - o] : 0;
        __syncthreads();
        sh[t] += u;
        __syncthreads();
    }
    if (i < NN) g_rowptr[i] = g_partpre[blockIdx.x] + sh[t] - v;
}
__global__ void k_csr_fill(const float* __restrict__ ew) {
    int e = blockIdx.x * blockDim.x + threadIdx.x;
    if (e >= NE) return;
    int s = g_src[e], d = g_dst[e];
    int pos = g_rowptr[d] + atomicAdd(&g_cur[d], 1);
    g_csrc[pos]  = s;
    g_ccoef[pos] = g_dinv[s] * ew[e] * g_dinv[d];
}

// ---------------- W -> tf32 in fragment-pair chunk layout ----------------------
__global__ void k_wprep(const float* __restrict__ W1, const float* __restrict__ W2) {
    int i = blockIdx.x * blockDim.x + threadIdx.x;
    if (i < NF * NH) {
        int k = i >> 6, n = i & 63;
        int ch = k >> 5, kin = k & 31;
        int w = ((ch * 16 + (kin >> 3) * 4 + (kin & 3)) << 7) + n * 2 + ((kin >> 2) & 1);
        g_bt1[w] = tf32_rna(W1[i]);
    } else if (i < NF * NH + NH * NH) {
        int j = i - NF * NH;
        int k = j >> 6, n = j & 63;
        int ch = k >> 5, kin = k & 31;
        int w = ((ch * 16 + (kin >> 3) * 4 + (kin & 3)) << 7) + n * 2 + ((kin >> 2) & 1);
        g_bt2[w] = tf32_rna(W2[j]);
    }
}

// ---------------- GEMM1: g_h/g_hh[M,64] = x[M,512] @ W1 ------------------------
__global__ __launch_bounds__(256)
void k_gemm_mma(const float* __restrict__ A, int K) {
    const unsigned* Bt = g_bt1;
    __shared__ float    As[2][128 * 36];
    __shared__ unsigned Bs[2][BCH];

    int tid  = threadIdx.x;
    int warp = tid >> 5;
    int lane = tid & 31;
    int grp  = lane >> 2;
    int tig  = lane & 3;
    int m0   = blockIdx.x * 128;
    int nc   = K >> 5;

    uint32_t asA = (uint32_t)__cvta_generic_to_shared(&As[0][0]);
    uint32_t asB = (uint32_t)__cvta_generic_to_shared(&Bs[0][0]);

    auto stage = [&](int ch) {
        int buf = ch & 1;
        int k0  = ch << 5;
        uint32_t ba = asA + buf * (128 * 36 * 4);
        uint32_t bb = asB + buf * (BCH * 4);
#pragma unroll
        for (int j = 0; j < 4; j++) {
            int q   = tid + j * 256;
            int row = q >> 3;
            int kk  = (q & 7) << 2;
            int gm  = m0 + row;
            if (gm >= NN) gm = NN - 1;
            cp_async16(ba + (row * 36 + kk) * 4, A + (size_t)gm * K + k0 + kk);
        }
#pragma unroll
        for (int j = 0; j < 2; j++) {
            int idx = tid + j * 256;
            int blk = idx >> 5;
            int off = (idx & 31) << 2;
            cp_async16(bb + (blk * BBLK + off) * 4,
                       Bt + (size_t)ch * BGCH + blk * 128 + off);
        }
    };

    float acc[8][4];
#pragma unroll
    for (int nt = 0; nt < 8; nt++)
#pragma unroll
        for (int c = 0; c < 4; c++) acc[nt][c] = 0.0f;

    stage(0);
    asm volatile("cp.async.commit_group;" ::: "memory");

    for (int ch = 0; ch < nc; ch++) {
        if (ch + 1 < nc) {
            stage(ch + 1);
            asm volatile("cp.async.commit_group;" ::: "memory");
            asm volatile("cp.async.wait_group 1;" ::: "memory");
        } else {
            asm volatile("cp.async.wait_group 0;" ::: "memory");
        }
        __syncthreads();

        int buf = ch & 1;
        const float*    sa = As[buf];
        const unsigned* sb = Bs[buf];
#pragma unroll
        for (int ks = 0; ks < 4; ks++) {
            int r = warp * 16 + grp;
            int k = ks * 8 + tig;
            unsigned a0 = tf32_rna(sa[r * 36 + k]);
            unsigned a1 = tf32_rna(sa[(r + 8) * 36 + k]);
            unsigned a2 = tf32_rna(sa[r * 36 + k + 4]);
            unsigned a3 = tf32_rna(sa[(r + 8) * 36 + k + 4]);
            const unsigned* bbase = sb + (ks * 4 + tig) * BBLK + grp * 2;
#pragma unroll
            for (int nt = 0; nt < 8; nt++) {
                uint2 bp = *(const uint2*)(bbase + nt * 16);
                asm volatile(
                    "mma.sync.aligned.m16n8k8.row.col.f32.tf32.tf32.f32 "
                    "{%0,%1,%2,%3}, {%4,%5,%6,%7}, {%8,%9}, {%0,%1,%2,%3};"
                    : "+f"(acc[nt][0]), "+f"(acc[nt][1]),
                      "+f"(acc[nt][2]), "+f"(acc[nt][3])
                    : "r"(a0), "r"(a1), "r"(a2), "r"(a3), "r"(bp.x), "r"(bp.y));
            }
        }
        __syncthreads();
    }

    int r0 = m0 + warp * 16 + grp;
    int r1 = r0 + 8;
#pragma unroll
    for (int nt = 0; nt < 8; nt++) {
        int cbase = nt * 8 + tig * 2;
        if (r0 < NN) {
            *(float2*)(g_h + (size_t)r0 * NH + cbase) = make_float2(acc[nt][0], acc[nt][1]);
            g_hh[(size_t)r0 * 32 + (cbase >> 1)] = __floats2half2_rn(acc[nt][0], acc[nt][1]);
        }
        if (r1 < NN) {
            *(float2*)(g_h + (size_t)r1 * NH + cbase) = make_float2(acc[nt][2], acc[nt][3]);
            g_hh[(size_t)r1 * 32 + (cbase >> 1)] = __floats2half2_rn(acc[nt][2], acc[nt][3]);
        }
    }
}

// ---- fp16 CSR gather core: 16 lanes, 4 halves per lane, ILP-4 -----------------
__device__ __forceinline__ void fma4h(uint2 p, float c, float& ax, float& ay,
                                      float& az, float& aw) {
    float2 f0 = __half22float2(*reinterpret_cast<const __half2*>(&p.x));
    float2 f1 = __half22float2(*reinterpret_cast<const __half2*>(&p.y));
    ax = fmaf(f0.x, c, ax); ay = fmaf(f0.y, c, ay);
    az = fmaf(f1.x, c, az); aw = fmaf(f1.y, c, aw);
}
__device__ __forceinline__ float4 gather_node_h(const __half2* __restrict__ src,
                                                int node, int l) {
    int beg = g_rowptr[node];
    int end = g_rowptr[node + 1];
    float ax = 0.f, ay = 0.f, az = 0.f, aw = 0.f;
    int i = beg;
    for (; i + 4 <= end; i += 4) {
        int   s0 = g_csrc[i],     s1 = g_csrc[i + 1];
        int   s2 = g_csrc[i + 2], s3 = g_csrc[i + 3];
        float c0 = g_ccoef[i],     c1 = g_ccoef[i + 1];
        float c2 = g_ccoef[i + 2], c3 = g_ccoef[i + 3];
        uint2 p0 = *(const uint2*)(src + (size_t)s0 * 32 + l * 2);
        uint2 p1 = *(const uint2*)(src + (size_t)s1 * 32 + l * 2);
        uint2 p2 = *(const uint2*)(src + (size_t)s2 * 32 + l * 2);
        uint2 p3 = *(const uint2*)(src + (size_t)s3 * 32 + l * 2);
        fma4h(p0, c0, ax, ay, az, aw);
        fma4h(p1, c1, ax, ay, az, aw);
        fma4h(p2, c2, ax, ay, az, aw);
        fma4h(p3, c3, ax, ay, az, aw);
    }
    for (; i < end; i++) {
        int   s = g_csrc[i];
        float c = g_ccoef[i];
        uint2 p = *(const uint2*)(src + (size_t)s * 32 + l * 2);
        fma4h(p, c, ax, ay, az, aw);
    }
    return make_float4(ax, ay, az, aw);
}

// ---------------- fused: agg1 + relu (into smem) + GEMM2 -> g_h2/g_hh2 ---------
__global__ __launch_bounds__(256)
void k_fused2(const float* __restrict__ bias) {
    __shared__ float    As[128 * 68];
    __shared__ unsigned Bs[2 * BCH];

    int tid  = threadIdx.x;
    int warp = tid >> 5;
    int lane = tid & 31;
    int grp  = lane >> 2;
    int tig  = lane & 3;
    int m0   = blockIdx.x * 128;

    uint32_t asB = (uint32_t)__cvta_generic_to_shared(&Bs[0]);
#pragma unroll
    for (int j = 0; j < 4; j++) {
        int idx = tid + j * 256;
        int ch  = idx >> 9;
        int r   = idx & 511;
        int blk = r >> 5;
        int off = (r & 31) << 2;
        cp_async16(asB + (ch * BCH + blk * BBLK + off) * 4,
                   g_bt2 + (size_t)ch * BGCH + blk * 128 + off);
    }
    asm volatile("cp.async.commit_group;" ::: "memory");

    // phase 1: aggregate 128 nodes (16 lanes/node, fp16 gather)
    int hw = tid >> 4;
    int l  = tid & 15;
#pragma unroll
    for (int pass = 0; pass < 8; pass++) {
        int node = m0 + pass * 16 + hw;
        float4 v = make_float4(0.f, 0.f, 0.f, 0.f);
        if (node < NN) {
            float4 a  = gather_node_h(g_hh, node, l);
            float  sc = g_selfc[node];
            float4 hd = *(const float4*)(g_h + (size_t)node * NH + l * 4);
            float4 b4 = *(const float4*)(bias + l * 4);
            v.x = fmaxf(fmaf(hd.x, sc, a.x) + b4.x, 0.f);
            v.y = fmaxf(fmaf(hd.y, sc, a.y) + b4.y, 0.f);
            v.z = fmaxf(fmaf(hd.z, sc, a.z) + b4.z, 0.f);
            v.w = fmaxf(fmaf(hd.w, sc, a.w) + b4.w, 0.f);
        }
        *(float4*)(&As[(pass * 16 + hw) * 68 + l * 4]) = v;
    }
    asm volatile("cp.async.wait_group 0;" ::: "memory");
    __syncthreads();

    // phase 2: GEMM K=64
    float acc[8][4];
#pragma unroll
    for (int nt = 0; nt < 8; nt++)
#pragma unroll
        for (int c = 0; c < 4; c++) acc[nt][c] = 0.0f;

#pragma unroll
    for (int ks = 0; ks < 8; ks++) {
        int ch  = ks >> 2;
        int ksl = ks & 3;
        int r = warp * 16 + grp;
        int k = ks * 8 + tig;
        unsigned a0 = tf32_rna(As[r * 68 + k]);
        unsigned a1 = tf32_rna(As[(r + 8) * 68 + k]);
        unsigned a2 = tf32_rna(As[r * 68 + k + 4]);
        unsigned a3 = tf32_rna(As[(r + 8) * 68 + k + 4]);
        const unsigned* bbase = Bs + ch * BCH + (ksl * 4 + tig) * BBLK + grp * 2;
#pragma unroll
        for (int nt = 0; nt < 8; nt++) {
            uint2 bp = *(const uint2*)(bbase + nt * 16);
            asm volatile(
                "mma.sync.aligned.m16n8k8.row.col.f32.tf32.tf32.f32 "
                "{%0,%1,%2,%3}, {%4,%5,%6,%7}, {%8,%9}, {%0,%1,%2,%3};"
                : "+f"(acc[nt][0]), "+f"(acc[nt][1]),
                  "+f"(acc[nt][2]), "+f"(acc[nt][3])
                : "r"(a0), "r"(a1), "r"(a2), "r"(a3), "r"(bp.x), "r"(bp.y));
        }
    }

    int r0 = m0 + warp * 16 + grp;
    int r1 = r0 + 8;
#pragma unroll
    for (int nt = 0; nt < 8; nt++) {
        int cbase = nt * 8 + tig * 2;
        if (r0 < NN) {
            *(float2*)(g_h2 + (size_t)r0 * NH + cbase) = make_float2(acc[nt][0], acc[nt][1]);
            g_hh2[(size_t)r0 * 32 + (cbase >> 1)] = __floats2half2_rn(acc[nt][0], acc[nt][1]);
        }
        if (r1 < NN) {
            *(float2*)(g_h2 + (size_t)r1 * NH + cbase) = make_float2(acc[nt][2], acc[nt][3]);
            g_hh2[(size_t)r1 * 32 + (cbase >> 1)] = __floats2half2_rn(acc[nt][2], acc[nt][3]);
        }
    }
}

// ---------------- final: agg2 + relu -> out (fp16 gather) -----------------------
__global__ __launch_bounds__(256)
void k_agg_final(const float* __restrict__ bias, float* __restrict__ outp) {
    int t    = blockIdx.x * 256 + threadIdx.x;
    int node = t >> 4;
    int l    = t & 15;
    if (node >= NN) return;
    float4 a  = gather_node_h(g_hh2, node, l);
    float  sc = g_selfc[node];
    float4 hd = *(const float4*)(g_h2 + (size_t)node * NH + l * 4);
    float4 b4 = *(const float4*)(bias + l * 4);
    float4 v;
    v.x = fmaxf(fmaf(hd.x, sc, a.x) + b4.x, 0.f);
    v.y = fmaxf(fmaf(hd.y, sc, a.y) + b4.y, 0.f);
    v.z = fmaxf(fmaf(hd.z, sc, a.z) + b4.z, 0.f);
    v.w = fmaxf(fmaf(hd.w, sc, a.w) + b4.w, 0.f);
    *(float4*)(outp + (size_t)node * NH + l * 4) = v;
}

extern "C" void kernel_launch(void* const* d_in, const int* in_sizes, int n_in,
                              void* d_out, int out_size) {
    const float* x  = (const float*)d_in[0];
    const void*  ei = (const void*)d_in[1];
    const float* ew = (const float*)d_in[2];
    const float* W1 = (const float*)d_in[3];
    const float* b1 = (const float*)d_in[4];
    const float* W2 = (const float*)d_in[5];
    const float* b2 = (const float*)d_in[6];
    float* out = (float*)d_out;

    static cudaStream_t s2 = nullptr;
    static cudaEvent_t  evF = nullptr, evJ = nullptr;
    static int init = 0, have_fork = 0;
    if (!init) {
        init = 1;
        if (cudaStreamCreateWithFlags(&s2, cudaStreamNonBlocking) == cudaSuccess &&
            cudaEventCreateWithFlags(&evF, cudaEventDisableTiming) == cudaSuccess &&
            cudaEventCreateWithFlags(&evJ, cudaEventDisableTiming) == cudaSuccess)
            have_fork = 1;
    }
    cudaStream_t sp = have_fork ? s2 : (cudaStream_t)0;

    const int NODE_BLKS  = (NN + 255) / 256;
    const int EDGE_BLKS  = (NE + 255) / 256;
    const int GEMM_BLKS  = (NN + 127) / 128;        // 391
    const int AGG_BLKS   = (NN * 16 + 255) / 256;
    const int WPREP_BLKS = (NF * NH + NH * NH + 255) / 256;

    if (have_fork) {
        cudaEventRecord(evF, 0);
        cudaStreamWaitEvent(s2, evF, 0);
    }
    k_prep0 <<<NODE_BLKS, 256, 0, sp>>>();
    k_detect<<<32, 256, 0, sp>>>((const int*)ei);

    k_wprep   <<<WPREP_BLKS, 256>>>(W1, W2);
    k_gemm_mma<<<GEMM_BLKS, 256>>>(x, NF);

    // prep chain hidden under GEMM1
    k_edge_prep<<<EDGE_BLKS, 256, 0, sp>>>(ei, ew);
    k_dinv     <<<NODE_BLKS, 256, 0, sp>>>();
    k_scanA    <<<NCHUNK, 256, 0, sp>>>();
    k_scanB    <<<1, 256, 0, sp>>>();
    k_scanC    <<<NCHUNK, 256, 0, sp>>>();
    k_csr_fill <<<EDGE_BLKS, 256, 0, sp>>>(ew);

    if (have_fork) {
        cudaEventRecord(evJ, s2);
        cudaStreamWaitEvent(0, evJ, 0);
    }

    k_fused2   <<<GEMM_BLKS, 256>>>(b1);       // agg1(fp16) + relu + GEMM2
    k_agg_final<<<AGG_BLKS, 256>>>(b2, out);   // agg2(fp16) + relu -> out
}

// round 16
// speedup vs baseline: 1.0540x; 1.0540x over previous
#include <cuda_runtime.h>
#include <cstdint>

#define NN 50000
#define NE 800000
#define NF 512
#define NH 64

// B chunk fragment-pair layout: 16 blocks (ks,tig) x 136 words (+8 skew)
#define BBLK 136
#define BCH  (16 * BBLK)            // 2176 words per chunk (padded)
#define BGCH 2048                   // words per chunk in global g_bt (unpadded)

// ---------------- scratch (static device globals; no runtime alloc) ---------
__device__ float    g_h [NN * NH];   // layer-1 linear output
__device__ float    g_h2[NN * NH];   // layer-2 linear output
__device__ float    g_deg  [NN];
__device__ float    g_dinv [NN];
__device__ float    g_selfc[NN];
__device__ int      g_src [NE];
__device__ int      g_dst [NE];
__device__ int      g_cnt [NN];
__device__ int      g_cur [NN];
__device__ int      g_rowptr[NN];
__device__ int      g_alloc;         // CSR slot allocator
__device__ int      g_csrc [NE];
__device__ float    g_ccoef[NE];
__device__ int      g_is32;
__device__ unsigned g_bt1[16 * BGCH]; // W1 tf32, fragment-pair chunk layout
__device__ unsigned g_bt2[2  * BGCH]; // W2 tf32, fragment-pair chunk layout

__device__ __forceinline__ unsigned tf32_rna(float f) {
    unsigned r;
    asm("cvt.rna.tf32.f32 %0, %1;" : "=r"(r) : "f"(f));
    return r;
}
__device__ __forceinline__ void cp_async16(uint32_t saddr, const void* gptr) {
    asm volatile("cp.async.cg.shared.global [%0], [%1], 16;"
                 :: "r"(saddr), "l"(gptr) : "memory");
}

// ---------------- prep kernel 1: init + dtype probe (merged) -------------------
__global__ void k_init(const int* __restrict__ ei32) {
    int i = blockIdx.x * blockDim.x + threadIdx.x;
    if (i == 0) g_alloc = 0;
    if (i < NN) { g_deg[i] = 1.0f; g_cnt[i] = 0; g_cur[i] = 0; }
    // block 0: OR-reduce odd 32-bit words of edge_index[0:8192]
    if (blockIdx.x == 0) {
        __shared__ int found;
        if (threadIdx.x == 0) found = 0;
        __syncthreads();
        int f = 0;
        for (int j = threadIdx.x; j < 8192; j += 256)
            if ((j & 1) == 1 && ei32[j] != 0) f = 1;
        if (f) atomicOr(&found, 1);
        __syncthreads();
        if (threadIdx.x == 0) g_is32 = found;
    }
}

// ---------------- prep kernel 2: edge decode + degree/count histograms ---------
__global__ void k_edge_prep(const void* __restrict__ eiv,
                            const float* __restrict__ ew) {
    int e = blockIdx.x * blockDim.x + threadIdx.x;
    if (e >= NE) return;
    int s, d;
    if (g_is32) {
        const int* p = (const int*)eiv;
        s = p[e]; d = p[NE + e];
    } else {
        const long long* p = (const long long*)eiv;
        s = (int)p[e]; d = (int)p[NE + e];
    }
    if ((unsigned)s >= NN) s = 0;
    if ((unsigned)d >= NN) d = 0;
    g_src[e] = s; g_dst[e] = d;
    atomicAdd(&g_deg[d], ew[e]);
    atomicAdd(&g_cnt[d], 1);
}

// ---------------- prep kernel 3: dinv/selfc + CSR slot allocation (merged) -----
// Per-block exclusive scan of cnt; one atomicAdd allocates the block's region.
// rowptr regions are disjoint+complete but non-monotone across blocks — gather
// only needs [rowptr, rowptr+cnt) per node, so output is unchanged.
__global__ void k_dinv_alloc() {
    __shared__ int sh[256];
    __shared__ int base;
    int i = blockIdx.x * 256 + threadIdx.x;
    int t = threadIdx.x;
    if (i < NN) {
        float dv = rsqrtf(g_deg[i]);
        g_dinv[i]  = dv;
        g_selfc[i] = dv * dv;
    }
    int v = (i < NN) ? g_cnt[i] : 0;
    sh[t] = v;
    __syncthreads();
#pragma unroll
    for (int o = 1; o < 256; o <<= 1) {
        int u = (t >= o) ? sh[t - o] : 0;
        __syncthreads();
        sh[t] += u;
        __syncthreads();
    }
    if (t == 255) base = atomicAdd(&g_alloc, sh[255]);
    __syncthreads();
    if (i < NN) g_rowptr[i] = base + sh[t] - v;
}

// ---------------- prep kernel 4: CSR fill (coef inline) ------------------------
__global__ void k_csr_fill(const float* __restrict__ ew) {
    int e = blockIdx.x * blockDim.x + threadIdx.x;
    if (e >= NE) return;
    int s = g_src[e], d = g_dst[e];
    int pos = g_rowptr[d] + atomicAdd(&g_cur[d], 1);
    g_csrc[pos]  = s;
    g_ccoef[pos] = g_dinv[s] * ew[e] * g_dinv[d];
}

// ---------------- W -> tf32 in fragment-pair chunk layout ----------------------
__global__ void k_wprep(const float* __restrict__ W1, const float* __restrict__ W2) {
    int i = blockIdx.x * blockDim.x + threadIdx.x;
    if (i < NF * NH) {
        int k = i >> 6, n = i & 63;
        int ch = k >> 5, kin = k & 31;
        int w = ((ch * 16 + (kin >> 3) * 4 + (kin & 3)) << 7) + n * 2 + ((kin >> 2) & 1);
        g_bt1[w] = tf32_rna(W1[i]);
    } else if (i < NF * NH + NH * NH) {
        int j = i - NF * NH;
        int k = j >> 6, n = j & 63;
        int ch = k >> 5, kin = k & 31;
        int w = ((ch * 16 + (kin >> 3) * 4 + (kin & 3)) << 7) + n * 2 + ((kin >> 2) & 1);
        g_bt2[w] = tf32_rna(W2[j]);
    }
}

// ---------------- GEMM1 (R9/R14 champion): g_h[M,64] = x[M,512] @ W1 -----------
__global__ __launch_bounds__(256)
void k_gemm_mma(const float* __restrict__ A, int K) {
    const unsigned* Bt = g_bt1;
    __shared__ float    As[2][128 * 36];
    __shared__ unsigned Bs[2][BCH];

    int tid  = threadIdx.x;
    int warp = tid >> 5;
    int lane = tid & 31;
    int grp  = lane >> 2;
    int tig  = lane & 3;
    int m0   = blockIdx.x * 128;
    int nc   = K >> 5;

    uint32_t asA = (uint32_t)__cvta_generic_to_shared(&As[0][0]);
    uint32_t asB = (uint32_t)__cvta_generic_to_shared(&Bs[0][0]);

    auto stage = [&](int ch) {
        int buf = ch & 1;
        int k0  = ch << 5;
        uint32_t ba = asA + buf * (128 * 36 * 4);
        uint32_t bb = asB + buf * (BCH * 4);
#pragma unroll
        for (int j = 0; j < 4; j++) {
            int q   = tid + j * 256;
            int row = q >> 3;
            int kk  = (q & 7) << 2;
            int gm  = m0 + row;
            if (gm >= NN) gm = NN - 1;
            cp_async16(ba + (row * 36 + kk) * 4, A + (size_t)gm * K + k0 + kk);
        }
#pragma unroll
        for (int j = 0; j < 2; j++) {
            int idx = tid + j * 256;
            int blk = idx >> 5;
            int off = (idx & 31) << 2;
            cp_async16(bb + (blk * BBLK + off) * 4,
                       Bt + (size_t)ch * BGCH + blk * 128 + off);
        }
    };

    float acc[8][4];
#pragma unroll
    for (int nt = 0; nt < 8; nt++)
#pragma unroll
        for (int c = 0; c < 4; c++) acc[nt][c] = 0.0f;

    stage(0);
    asm volatile("cp.async.commit_group;" ::: "memory");

    for (int ch = 0; ch < nc; ch++) {
        if (ch + 1 < nc) {
            stage(ch + 1);
            asm volatile("cp.async.commit_group;" ::: "memory");
            asm volatile("cp.async.wait_group 1;" ::: "memory");
        } else {
            asm volatile("cp.async.wait_group 0;" ::: "memory");
        }
        __syncthreads();

        int buf = ch & 1;
        const float*    sa = As[buf];
        const unsigned* sb = Bs[buf];
#pragma unroll
        for (int ks = 0; ks < 4; ks++) {
            int r = warp * 16 + grp;
            int k = ks * 8 + tig;
            unsigned a0 = tf32_rna(sa[r * 36 + k]);
            unsigned a1 = tf32_rna(sa[(r + 8) * 36 + k]);
            unsigned a2 = tf32_rna(sa[r * 36 + k + 4]);
            unsigned a3 = tf32_rna(sa[(r + 8) * 36 + k + 4]);
            const unsigned* bbase = sb + (ks * 4 + tig) * BBLK + grp * 2;
#pragma unroll
            for (int nt = 0; nt < 8; nt++) {
                uint2 bp = *(const uint2*)(bbase + nt * 16);
                asm volatile(
                    "mma.sync.aligned.m16n8k8.row.col.f32.tf32.tf32.f32 "
                    "{%0,%1,%2,%3}, {%4,%5,%6,%7}, {%8,%9}, {%0,%1,%2,%3};"
                    : "+f"(acc[nt][0]), "+f"(acc[nt][1]),
                      "+f"(acc[nt][2]), "+f"(acc[nt][3])
                    : "r"(a0), "r"(a1), "r"(a2), "r"(a3), "r"(bp.x), "r"(bp.y));
            }
        }
        __syncthreads();
    }

    int r0 = m0 + warp * 16 + grp;
    int r1 = r0 + 8;
#pragma unroll
    for (int nt = 0; nt < 8; nt++) {
        int cbase = nt * 8 + tig * 2;
        if (r0 < NN)
            *(float2*)(g_h + (size_t)r0 * NH + cbase) = make_float2(acc[nt][0], acc[nt][1]);
        if (r1 < NN)
            *(float2*)(g_h + (size_t)r1 * NH + cbase) = make_float2(acc[nt][2], acc[nt][3]);
    }
}

// ---- ILP-4 CSR gather core: 16 lanes, float4 per lane -------------------------
__device__ __forceinline__ float4 gather_node(const float* __restrict__ src,
                                              int node, int l) {
    int beg = g_rowptr[node];
    int end = beg + g_cnt[node];
    float ax = 0.f, ay = 0.f, az = 0.f, aw = 0.f;
    int i = beg;
    for (; i + 4 <= end; i += 4) {
        int   s0 = g_csrc[i],     s1 = g_csrc[i + 1];
        int   s2 = g_csrc[i + 2], s3 = g_csrc[i + 3];
        float c0 = g_ccoef[i],     c1 = g_ccoef[i + 1];
        float c2 = g_ccoef[i + 2], c3 = g_ccoef[i + 3];
        float4 h0 = *(const float4*)(src + (size_t)s0 * NH + l * 4);
        float4 h1 = *(const float4*)(src + (size_t)s1 * NH + l * 4);
        float4 h2 = *(const float4*)(src + (size_t)s2 * NH + l * 4);
        float4 h3 = *(const float4*)(src + (size_t)s3 * NH + l * 4);
        ax = fmaf(h0.x, c0, ax); ay = fmaf(h0.y, c0, ay);
        az = fmaf(h0.z, c0, az); aw = fmaf(h0.w, c0, aw);
        ax = fmaf(h1.x, c1, ax); ay = fmaf(h1.y, c1, ay);
        az = fmaf(h1.z, c1, az); aw = fmaf(h1.w, c1, aw);
        ax = fmaf(h2.x, c2, ax); ay = fmaf(h2.y, c2, ay);
        az = fmaf(h2.z, c2, az); aw = fmaf(h2.w, c2, aw);
        ax = fmaf(h3.x, c3, ax); ay = fmaf(h3.y, c3, ay);
        az = fmaf(h3.z, c3, az); aw = fmaf(h3.w, c3, aw);
    }
    for (; i < end; i++) {
        int   s = g_csrc[i];
        float c = g_ccoef[i];
        float4 h4 = *(const float4*)(src + (size_t)s * NH + l * 4);
        ax = fmaf(h4.x, c, ax); ay = fmaf(h4.y, c, ay);
        az = fmaf(h4.z, c, az); aw = fmaf(h4.w, c, aw);
    }
    return make_float4(ax, ay, az, aw);
}

// ---------------- fused: agg1 + relu (into smem) + GEMM2 -> g_h2 ---------------
__global__ __launch_bounds__(256)
void k_fused2(const float* __restrict__ bias) {
    __shared__ float    As[128 * 68];
    __shared__ unsigned Bs[2 * BCH];

    int tid  = threadIdx.x;
    int warp = tid >> 5;
    int lane = tid & 31;
    int grp  = lane >> 2;
    int tig  = lane & 3;
    int m0   = blockIdx.x * 128;

    uint32_t asB = (uint32_t)__cvta_generic_to_shared(&Bs[0]);
#pragma unroll
    for (int j = 0; j < 4; j++) {
        int idx = tid + j * 256;
        int ch  = idx >> 9;
        int r   = idx & 511;
        int blk = r >> 5;
        int off = (r & 31) << 2;
        cp_async16(asB + (ch * BCH + blk * BBLK + off) * 4,
                   g_bt2 + (size_t)ch * BGCH + blk * 128 + off);
    }
    asm volatile("cp.async.commit_group;" ::: "memory");

    int hw = tid >> 4;
    int l  = tid & 15;
#pragma unroll
    for (int pass = 0; pass < 8; pass++) {
        int node = m0 + pass * 16 + hw;
        float4 v = make_float4(0.f, 0.f, 0.f, 0.f);
        if (node < NN) {
            float4 a  = gather_node(g_h, node, l);
            float  sc = g_selfc[node];
            float4 hd = *(const float4*)(g_h + (size_t)node * NH + l * 4);
            float4 b4 = *(const float4*)(bias + l * 4);
            v.x = fmaxf(fmaf(hd.x, sc, a.x) + b4.x, 0.f);
            v.y = fmaxf(fmaf(hd.y, sc, a.y) + b4.y, 0.f);
            v.z = fmaxf(fmaf(hd.z, sc, a.z) + b4.z, 0.f);
            v.w = fmaxf(fmaf(hd.w, sc, a.w) + b4.w, 0.f);
        }
        *(float4*)(&As[(pass * 16 + hw) * 68 + l * 4]) = v;
    }
    asm volatile("cp.async.wait_group 0;" ::: "memory");
    __syncthreads();

    float acc[8][4];
#pragma unroll
    for (int nt = 0; nt < 8; nt++)
#pragma unroll
        for (int c = 0; c < 4; c++) acc[nt][c] = 0.0f;

#pragma unroll
    for (int ks = 0; ks < 8; ks++) {
        int ch  = ks >> 2;
        int ksl = ks & 3;
        int r = warp * 16 + grp;
        int k = ks * 8 + tig;
        unsigned a0 = tf32_rna(As[r * 68 + k]);
        unsigned a1 = tf32_rna(As[(r + 8) * 68 + k]);
        unsigned a2 = tf32_rna(As[r * 68 + k + 4]);
        unsigned a3 = tf32_rna(As[(r + 8) * 68 + k + 4]);
        const unsigned* bbase = Bs + ch * BCH + (ksl * 4 + tig) * BBLK + grp * 2;
#pragma unroll
        for (int nt = 0; nt < 8; nt++) {
            uint2 bp = *(const uint2*)(bbase + nt * 16);
            asm volatile(
                "mma.sync.aligned.m16n8k8.row.col.f32.tf32.tf32.f32 "
                "{%0,%1,%2,%3}, {%4,%5,%6,%7}, {%8,%9}, {%0,%1,%2,%3};"
                : "+f"(acc[nt][0]), "+f"(acc[nt][1]),
                  "+f"(acc[nt][2]), "+f"(acc[nt][3])
                : "r"(a0), "r"(a1), "r"(a2), "r"(a3), "r"(bp.x), "r"(bp.y));
        }
    }

    int r0 = m0 + warp * 16 + grp;
    int r1 = r0 + 8;
#pragma unroll
    for (int nt = 0; nt < 8; nt++) {
        int cbase = nt * 8 + tig * 2;
        if (r0 < NN)
            *(float2*)(g_h2 + (size_t)r0 * NH + cbase) = make_float2(acc[nt][0], acc[nt][1]);
        if (r1 < NN)
            *(float2*)(g_h2 + (size_t)r1 * NH + cbase) = make_float2(acc[nt][2], acc[nt][3]);
    }
}

// ---------------- final: agg2 + relu -> out -------------------------------------
__global__ __launch_bounds__(256)
void k_agg_final(const float* __restrict__ bias, float* __restrict__ outp) {
    int t    = blockIdx.x * 256 + threadIdx.x;
    int node = t >> 4;
    int l    = t & 15;
    if (node >= NN) return;
    float4 a  = gather_node(g_h2, node, l);
    float  sc = g_selfc[node];
    float4 hd = *(const float4*)(g_h2 + (size_t)node * NH + l * 4);
    float4 b4 = *(const float4*)(bias + l * 4);
    float4 v;
    v.x = fmaxf(fmaf(hd.x, sc, a.x) + b4.x, 0.f);
    v.y = fmaxf(fmaf(hd.y, sc, a.y) + b4.y, 0.f);
    v.z = fmaxf(fmaf(hd.z, sc, a.z) + b4.z, 0.f);
    v.w = fmaxf(fmaf(hd.w, sc, a.w) + b4.w, 0.f);
    *(float4*)(outp + (size_t)node * NH + l * 4) = v;
}

extern "C" void kernel_launch(void* const* d_in, const int* in_sizes, int n_in,
                              void* d_out, int out_size) {
    const float* x  = (const float*)d_in[0];
    const void*  ei = (const void*)d_in[1];
    const float* ew = (const float*)d_in[2];
    const float* W1 = (const float*)d_in[3];
    const float* b1 = (const float*)d_in[4];
    const float* W2 = (const float*)d_in[5];
    const float* b2 = (const float*)d_in[6];
    float* out = (float*)d_out;

    static cudaStream_t s2 = nullptr;
    static cudaEvent_t  evF = nullptr, evJ = nullptr;
    static int init = 0, have_fork = 0;
    if (!init) {
        init = 1;
        if (cudaStreamCreateWithFlags(&s2, cudaStreamNonBlocking) == cudaSuccess &&
            cudaEventCreateWithFlags(&evF, cudaEventDisableTiming) == cudaSuccess &&
            cudaEventCreateWithFlags(&evJ, cudaEventDisableTiming) == cudaSuccess)
            have_fork = 1;
    }
    cudaStream_t sp = have_fork ? s2 : (cudaStream_t)0;

    const int NODE_BLKS  = (NN + 255) / 256;
    const int EDGE_BLKS  = (NE + 255) / 256;
    const int GEMM_BLKS  = (NN + 127) / 128;        // 391
    const int AGG_BLKS   = (NN * 16 + 255) / 256;
    const int WPREP_BLKS = (NF * NH + NH * NH + 255) / 256;

    if (have_fork) {
        cudaEventRecord(evF, 0);
        cudaStreamWaitEvent(s2, evF, 0);
    }
    // prep chain: 4 kernels total on the side stream
    k_init     <<<NODE_BLKS, 256, 0, sp>>>((const int*)ei);
    k_edge_prep<<<EDGE_BLKS, 256, 0, sp>>>(ei, ew);

    k_wprep   <<<WPREP_BLKS, 256>>>(W1, W2);
    k_gemm_mma<<<GEMM_BLKS, 256>>>(x, NF);

    k_dinv_alloc<<<NODE_BLKS, 256, 0, sp>>>();
    k_csr_fill  <<<EDGE_BLKS, 256, 0, sp>>>(ew);

    if (have_fork) {
        cudaEventRecord(evJ, s2);
        cudaStreamWaitEvent(0, evJ, 0);
    }

    k_fused2   <<<GEMM_BLKS, 256>>>(b1);       // agg1 + relu + GEMM2 -> g_h2
    k_agg_final<<<AGG_BLKS, 256>>>(b2, out);   // agg2 + relu -> out
}

// round 17
// speedup vs baseline: 1.1202x; 1.0628x over previous
#include <cuda_runtime.h>
#include <cuda_fp16.h>
#include <cstdint>

#define NN 50000
#define NE 800000
#define NF 512
#define NH 64

// fp16 B layout: per k32-chunk, 8 blocks (ks2*4+tig) x 128 data words,
// skewed to 136 words in smem. word = half2 {W[k][n], W[k+1][n]};
// within block: word index = n*2 + i, where k = 32ch + 16ks2 + 2tig + 8i.
#define BBLK 136
#define BH   (8 * BBLK)             // 1088 words per chunk (smem, padded)
#define BG   1024                   // words per chunk (global, unpadded)
#define AH   40                     // GEMM1 A pitch (halves)
#define AH2  72                     // GEMM2 A pitch (halves)

// ---------------- scratch (static device globals; no runtime alloc) ---------
__device__ float    g_h [NN * NH];   // layer-1 linear output
__device__ float    g_h2[NN * NH];   // layer-2 linear output
__device__ float    g_deg  [NN];
__device__ float    g_dinv [NN];
__device__ float    g_selfc[NN];
__device__ int      g_src [NE];
__device__ int      g_dst [NE];
__device__ int      g_cnt [NN];
__device__ int      g_cur [NN];
__device__ int      g_rowptr[NN];
__device__ int      g_alloc;
__device__ int      g_csrc [NE];
__device__ float    g_ccoef[NE];
__device__ int      g_is32;
__device__ unsigned g_bt1[16 * BG];  // W1 fp16 pairs, block layout
__device__ unsigned g_bt2[2  * BG];  // W2 fp16 pairs, block layout

__device__ __forceinline__ void cp_async16(uint32_t saddr, const void* gptr) {
    asm volatile("cp.async.cg.shared.global [%0], [%1], 16;"
                 :: "r"(saddr), "l"(gptr) : "memory");
}
#define MMA16(acc, a0, a1, a2, a3, b0, b1)                                   \
    asm volatile(                                                            \
        "mma.sync.aligned.m16n8k16.row.col.f32.f16.f16.f32 "                 \
        "{%0,%1,%2,%3}, {%4,%5,%6,%7}, {%8,%9}, {%0,%1,%2,%3};"              \
        : "+f"((acc)[0]), "+f"((acc)[1]), "+f"((acc)[2]), "+f"((acc)[3])     \
        : "r"(a0), "r"(a1), "r"(a2), "r"(a3), "r"(b0), "r"(b1))

// ---------------- prep kernel 1: init + dtype probe ---------------------------
__global__ void k_init(const int* __restrict__ ei32) {
    int i = blockIdx.x * blockDim.x + threadIdx.x;
    if (i == 0) g_alloc = 0;
    if (i < NN) { g_deg[i] = 1.0f; g_cnt[i] = 0; g_cur[i] = 0; }
    if (blockIdx.x == 0) {
        __shared__ int found;
        if (threadIdx.x == 0) found = 0;
        __syncthreads();
        int f = 0;
        for (int j = threadIdx.x; j < 8192; j += 256)
            if ((j & 1) == 1 && ei32[j] != 0) f = 1;
        if (f) atomicOr(&found, 1);
        __syncthreads();
        if (threadIdx.x == 0) g_is32 = found;
    }
}

// ---------------- prep kernel 2: edge decode + histograms ---------------------
__global__ void k_edge_prep(const void* __restrict__ eiv,
                            const float* __restrict__ ew) {
    int e = blockIdx.x * blockDim.x + threadIdx.x;
    if (e >= NE) return;
    int s, d;
    if (g_is32) {
        const int* p = (const int*)eiv;
        s = p[e]; d = p[NE + e];
    } else {
        const long long* p = (const long long*)eiv;
        s = (int)p[e]; d = (int)p[NE + e];
    }
    if ((unsigned)s >= NN) s = 0;
    if ((unsigned)d >= NN) d = 0;
    g_src[e] = s; g_dst[e] = d;
    atomicAdd(&g_deg[d], ew[e]);
    atomicAdd(&g_cnt[d], 1);
}

// ---------------- prep kernel 3: dinv/selfc + CSR slot allocation --------------
__global__ void k_dinv_alloc() {
    __shared__ int sh[256];
    __shared__ int base;
    int i = blockIdx.x * 256 + threadIdx.x;
    int t = threadIdx.x;
    if (i < NN) {
        float dv = rsqrtf(g_deg[i]);
        g_dinv[i]  = dv;
        g_selfc[i] = dv * dv;
    }
    int v = (i < NN) ? g_cnt[i] : 0;
    sh[t] = v;
    __syncthreads();
#pragma unroll
    for (int o = 1; o < 256; o <<= 1) {
        int u = (t >= o) ? sh[t - o] : 0;
        __syncthreads();
        sh[t] += u;
        __syncthreads();
    }
    if (t == 255) base = atomicAdd(&g_alloc, sh[255]);
    __syncthreads();
    if (i < NN) g_rowptr[i] = base + sh[t] - v;
}

// ---------------- prep kernel 4: CSR fill --------------------------------------
__global__ void k_csr_fill(const float* __restrict__ ew) {
    int e = blockIdx.x * blockDim.x + threadIdx.x;
    if (e >= NE) return;
    int s = g_src[e], d = g_dst[e];
    int pos = g_rowptr[d] + atomicAdd(&g_cur[d], 1);
    g_csrc[pos]  = s;
    g_ccoef[pos] = g_dinv[s] * ew[e] * g_dinv[d];
}

// ---------------- W -> fp16 pair words in block layout --------------------------
__global__ void k_wprep(const float* __restrict__ W1, const float* __restrict__ W2) {
    int w = blockIdx.x * blockDim.x + threadIdx.x;
    if (w < 16 * BG) {
        int ch = w >> 10, r = w & 1023;
        int blk = r >> 7, n2 = r & 127;
        int n = n2 >> 1, i = n2 & 1;
        int ks2 = blk >> 2, tig = blk & 3;
        int k = ch * 32 + ks2 * 16 + tig * 2 + i * 8;
        __half2 h = __floats2half2_rn(W1[(size_t)k * NH + n], W1[(size_t)(k + 1) * NH + n]);
        g_bt1[w] = *(unsigned*)&h;
    } else if (w < 16 * BG + 2 * BG) {
        int j = w - 16 * BG;
        int ch = j >> 10, r = j & 1023;
        int blk = r >> 7, n2 = r & 127;
        int n = n2 >> 1, i = n2 & 1;
        int ks2 = blk >> 2, tig = blk & 3;
        int k = ch * 32 + ks2 * 16 + tig * 2 + i * 8;
        __half2 h = __floats2half2_rn(W2[(size_t)k * NH + n], W2[(size_t)(k + 1) * NH + n]);
        g_bt2[j] = *(unsigned*)&h;
    }
}

// ---------------- GEMM1 fp16: g_h[M,64] = x[M,512] @ W1 ------------------------
// A: LDG float4 -> cvt fp16 -> STS (register double-buffered). B: cp.async.
// As pad AH=40: a-frag bank = (20r + tig) mod 32 -> conflict-free.
__global__ __launch_bounds__(256)
void k_gemm_mma(const float* __restrict__ A, int K) {
    __shared__ __half   As[2][128 * AH];
    __shared__ unsigned Bs[2][BH];

    int tid  = threadIdx.x;
    int warp = tid >> 5;
    int lane = tid & 31;
    int grp  = lane >> 2;
    int tig  = lane & 3;
    int m0   = blockIdx.x * 128;
    int nc   = K >> 5;

    uint32_t asB = (uint32_t)__cvta_generic_to_shared(&Bs[0][0]);

    float4 rA[4];
    auto ldA = [&](int ch) {
        int k0 = ch << 5;
#pragma unroll
        for (int j = 0; j < 4; j++) {
            int q   = tid + j * 256;
            int row = q >> 3;
            int kf  = (q & 7) << 2;
            int gm  = m0 + row;
            if (gm >= NN) gm = NN - 1;
            rA[j] = *(const float4*)(A + (size_t)gm * K + k0 + kf);
        }
    };
    auto stsA = [&](int buf) {
#pragma unroll
        for (int j = 0; j < 4; j++) {
            int q   = tid + j * 256;
            int row = q >> 3;
            int kf  = (q & 7) << 2;
            __half2 h0 = __floats2half2_rn(rA[j].x, rA[j].y);
            __half2 h1 = __floats2half2_rn(rA[j].z, rA[j].w);
            *(uint2*)(&As[buf][row * AH + kf]) =
                make_uint2(*(unsigned*)&h0, *(unsigned*)&h1);
        }
    };
    auto cpB = [&](int ch) {
        int buf = ch & 1;
        int blk = tid >> 5;
        int off = (tid & 31) << 2;
        cp_async16(asB + (buf * BH + blk * BBLK + off) * 4,
                   g_bt1 + (size_t)ch * BG + blk * 128 + off);
    };

    float acc[8][4];
#pragma unroll
    for (int nt = 0; nt < 8; nt++)
#pragma unroll
        for (int c = 0; c < 4; c++) acc[nt][c] = 0.0f;

    ldA(0);
    cpB(0);
    asm volatile("cp.async.commit_group;" ::: "memory");

    for (int ch = 0; ch < nc; ch++) {
        int buf = ch & 1;
        stsA(buf);
        if (ch + 1 < nc) {
            ldA(ch + 1);
            cpB(ch + 1);
            asm volatile("cp.async.commit_group;" ::: "memory");
            asm volatile("cp.async.wait_group 1;" ::: "memory");
        } else {
            asm volatile("cp.async.wait_group 0;" ::: "memory");
        }
        __syncthreads();

        const __half*   sa = As[buf];
        const unsigned* sb = Bs[buf];
        int r = warp * 16 + grp;
#pragma unroll
        for (int ks2 = 0; ks2 < 2; ks2++) {
            int kb = ks2 * 16 + 2 * tig;
            unsigned a0 = *(const unsigned*)&sa[r * AH + kb];
            unsigned a1 = *(const unsigned*)&sa[(r + 8) * AH + kb];
            unsigned a2 = *(const unsigned*)&sa[r * AH + kb + 8];
            unsigned a3 = *(const unsigned*)&sa[(r + 8) * AH + kb + 8];
            const unsigned* bbase = sb + (ks2 * 4 + tig) * BBLK + grp * 2;
#pragma unroll
            for (int nt = 0; nt < 8; nt++) {
                uint2 bp = *(const uint2*)(bbase + nt * 16);
                MMA16(acc[nt], a0, a1, a2, a3, bp.x, bp.y);
            }
        }
        __syncthreads();
    }

    int r0 = m0 + warp * 16 + grp;
    int r1 = r0 + 8;
#pragma unroll
    for (int nt = 0; nt < 8; nt++) {
        int cbase = nt * 8 + tig * 2;
        if (r0 < NN)
            *(float2*)(g_h + (size_t)r0 * NH + cbase) = make_float2(acc[nt][0], acc[nt][1]);
        if (r1 < NN)
            *(float2*)(g_h + (size_t)r1 * NH + cbase) = make_float2(acc[nt][2], acc[nt][3]);
    }
}

// ---- ILP-4 CSR gather core (fp32): 16 lanes, float4 per lane ------------------
__device__ __forceinline__ float4 gather_node(const float* __restrict__ src,
                                              int node, int l) {
    int beg = g_rowptr[node];
    int end = beg + g_cnt[node];
    float ax = 0.f, ay = 0.f, az = 0.f, aw = 0.f;
    int i = beg;
    for (; i + 4 <= end; i += 4) {
        int   s0 = g_csrc[i],     s1 = g_csrc[i + 1];
        int   s2 = g_csrc[i + 2], s3 = g_csrc[i + 3];
        float c0 = g_ccoef[i],     c1 = g_ccoef[i + 1];
        float c2 = g_ccoef[i + 2], c3 = g_ccoef[i + 3];
        float4 h0 = *(const float4*)(src + (size_t)s0 * NH + l * 4);
        float4 h1 = *(const float4*)(src + (size_t)s1 * NH + l * 4);
        float4 h2 = *(const float4*)(src + (size_t)s2 * NH + l * 4);
        float4 h3 = *(const float4*)(src + (size_t)s3 * NH + l * 4);
        ax = fmaf(h0.x, c0, ax); ay = fmaf(h0.y, c0, ay);
        az = fmaf(h0.z, c0, az); aw = fmaf(h0.w, c0, aw);
        ax = fmaf(h1.x, c1, ax); ay = fmaf(h1.y, c1, ay);
        az = fmaf(h1.z, c1, az); aw = fmaf(h1.w, c1, aw);
        ax = fmaf(h2.x, c2, ax); ay = fmaf(h2.y, c2, ay);
        az = fmaf(h2.z, c2, az); aw = fmaf(h2.w, c2, aw);
        ax = fmaf(h3.x, c3, ax); ay = fmaf(h3.y, c3, ay);
        az = fmaf(h3.z, c3, az); aw = fmaf(h3.w, c3, aw);
    }
    for (; i < end; i++) {
        int   s = g_csrc[i];
        float c = g_ccoef[i];
        float4 h4 = *(const float4*)(src + (size_t)s * NH + l * 4);
        ax = fmaf(h4.x, c, ax); ay = fmaf(h4.y, c, ay);
        az = fmaf(h4.z, c, az); aw = fmaf(h4.w, c, aw);
    }
    return make_float4(ax, ay, az, aw);
}

// ---------------- fused: agg1 + relu (fp16 into smem) + GEMM2 -> g_h2 ----------
// As2 pad AH2=72: a-frag bank = (4r + tig + const) mod 32 -> conflict-free.
__global__ __launch_bounds__(256)
void k_fused2(const float* __restrict__ bias) {
    __shared__ __half   As[128 * AH2];
    __shared__ unsigned Bs[2 * BH];

    int tid  = threadIdx.x;
    int warp = tid >> 5;
    int lane = tid & 31;
    int grp  = lane >> 2;
    int tig  = lane & 3;
    int m0   = blockIdx.x * 128;

    uint32_t asB = (uint32_t)__cvta_generic_to_shared(&Bs[0]);
    // prefetch both B2 chunks: 2048 words = 512 x 16B
#pragma unroll
    for (int j = 0; j < 2; j++) {
        int idx = tid + j * 256;          // 0..511
        int ch  = idx >> 8;
        int r   = idx & 255;
        int blk = r >> 5;
        int off = (r & 31) << 2;
        cp_async16(asB + (ch * BH + blk * BBLK + off) * 4,
                   g_bt2 + (size_t)ch * BG + blk * 128 + off);
    }
    asm volatile("cp.async.commit_group;" ::: "memory");

    // phase 1: aggregate 128 nodes; write relu result as fp16 into A tile
    int hw = tid >> 4;
    int l  = tid & 15;
#pragma unroll
    for (int pass = 0; pass < 8; pass++) {
        int node = m0 + pass * 16 + hw;
        float4 v = make_float4(0.f, 0.f, 0.f, 0.f);
        if (node < NN) {
            float4 a  = gather_node(g_h, node, l);
            float  sc = g_selfc[node];
            float4 hd = *(const float4*)(g_h + (size_t)node * NH + l * 4);
            float4 b4 = *(const float4*)(bias + l * 4);
            v.x = fmaxf(fmaf(hd.x, sc, a.x) + b4.x, 0.f);
            v.y = fmaxf(fmaf(hd.y, sc, a.y) + b4.y, 0.f);
            v.z = fmaxf(fmaf(hd.z, sc, a.z) + b4.z, 0.f);
            v.w = fmaxf(fmaf(hd.w, sc, a.w) + b4.w, 0.f);
        }
        __half2 h0 = __floats2half2_rn(v.x, v.y);
        __half2 h1 = __floats2half2_rn(v.z, v.w);
        *(uint2*)(&As[(pass * 16 + hw) * AH2 + l * 4]) =
            make_uint2(*(unsigned*)&h0, *(unsigned*)&h1);
    }
    asm volatile("cp.async.wait_group 0;" ::: "memory");
    __syncthreads();

    // phase 2: fp16 GEMM K=64 (2 chunks x 2 ks2)
    float acc[8][4];
#pragma unroll
    for (int nt = 0; nt < 8; nt++)
#pragma unroll
        for (int c = 0; c < 4; c++) acc[nt][c] = 0.0f;

    int r = warp * 16 + grp;
#pragma unroll
    for (int ks = 0; ks < 4; ks++) {
        int ch  = ks >> 1;
        int ks2 = ks & 1;
        int kb  = ch * 32 + ks2 * 16 + 2 * tig;
        unsigned a0 = *(const unsigned*)&As[r * AH2 + kb];
        unsigned a1 = *(const unsigned*)&As[(r + 8) * AH2 + kb];
        unsigned a2 = *(const unsigned*)&As[r * AH2 + kb + 8];
        unsigned a3 = *(const unsigned*)&As[(r + 8) * AH2 + kb + 8];
        const unsigned* bbase = Bs + ch * BH + (ks2 * 4 + tig) * BBLK + grp * 2;
#pragma unroll
        for (int nt = 0; nt < 8; nt++) {
            uint2 bp = *(const uint2*)(bbase + nt * 16);
            MMA16(acc[nt], a0, a1, a2, a3, bp.x, bp.y);
        }
    }

    int r0 = m0 + r;
    int r1 = r0 + 8;
#pragma unroll
    for (int nt = 0; nt < 8; nt++) {
        int cbase = nt * 8 + tig * 2;
        if (r0 < NN)
            *(float2*)(g_h2 + (size_t)r0 * NH + cbase) = make_float2(acc[nt][0], acc[nt][1]);
        if (r1 < NN)
            *(float2*)(g_h2 + (size_t)r1 * NH + cbase) = make_float2(acc[nt][2], acc[nt][3]);
    }
}

// ---------------- final: agg2 + relu -> out -------------------------------------
__global__ __launch_bounds__(256)
void k_agg_final(const float* __restrict__ bias, float* __restrict__ outp) {
    int t    = blockIdx.x * 256 + threadIdx.x;
    int node = t >> 4;
    int l    = t & 15;
    if (node >= NN) return;
    float4 a  = gather_node(g_h2, node, l);
    float  sc = g_selfc[node];
    float4 hd = *(const float4*)(g_h2 + (size_t)node * NH + l * 4);
    float4 b4 = *(const float4*)(bias + l * 4);
    float4 v;
    v.x = fmaxf(fmaf(hd.x, sc, a.x) + b4.x, 0.f);
    v.y = fmaxf(fmaf(hd.y, sc, a.y) + b4.y, 0.f);
    v.z = fmaxf(fmaf(hd.z, sc, a.z) + b4.z, 0.f);
    v.w = fmaxf(fmaf(hd.w, sc, a.w) + b4.w, 0.f);
    *(float4*)(outp + (size_t)node * NH + l * 4) = v;
}

extern "C" void kernel_launch(void* const* d_in, const int* in_sizes, int n_in,
                              void* d_out, int out_size) {
    const float* x  = (const float*)d_in[0];
    const void*  ei = (const void*)d_in[1];
    const float* ew = (const float*)d_in[2];
    const float* W1 = (const float*)d_in[3];
    const float* b1 = (const float*)d_in[4];
    const float* W2 = (const float*)d_in[5];
    const float* b2 = (const float*)d_in[6];
    float* out = (float*)d_out;

    static cudaStream_t s2 = nullptr;
    static cudaEvent_t  evF = nullptr, evJ = nullptr;
    static int init = 0, have_fork = 0;
    if (!init) {
        init = 1;
        if (cudaStreamCreateWithFlags(&s2, cudaStreamNonBlocking) == cudaSuccess &&
            cudaEventCreateWithFlags(&evF, cudaEventDisableTiming) == cudaSuccess &&
            cudaEventCreateWithFlags(&evJ, cudaEventDisableTiming) == cudaSuccess)
            have_fork = 1;
    }
    cudaStream_t sp = have_fork ? s2 : (cudaStream_t)0;

    const int NODE_BLKS  = (NN + 255) / 256;
    const int EDGE_BLKS  = (NE + 255) / 256;
    const int GEMM_BLKS  = (NN + 127) / 128;        // 391
    const int AGG_BLKS   = (NN * 16 + 255) / 256;
    const int WPREP_BLKS = (16 * BG + 2 * BG + 255) / 256;

    if (have_fork) {
        cudaEventRecord(evF, 0);
        cudaStreamWaitEvent(s2, evF, 0);
    }
    k_init     <<<NODE_BLKS, 256, 0, sp>>>((const int*)ei);
    k_edge_prep<<<EDGE_BLKS, 256, 0, sp>>>(ei, ew);

    k_wprep   <<<WPREP_BLKS, 256>>>(W1, W2);
    k_gemm_mma<<<GEMM_BLKS, 256>>>(x, NF);

    k_dinv_alloc<<<NODE_BLKS, 256, 0, sp>>>();
    k_csr_fill  <<<EDGE_BLKS, 256, 0, sp>>>(ew);

    if (have_fork) {
        cudaEventRecord(evJ, s2);
        cudaStreamWaitEvent(0, evJ, 0);
    }

    k_fused2   <<<GEMM_BLKS, 256>>>(b1);       // agg1 + relu + GEMM2(fp16)
    k_agg_final<<<AGG_BLKS, 256>>>(b2, out);   // agg2 + relu -> out
}